// round 11
// baseline (speedup 1.0000x reference)
#include <cuda_runtime.h>
#include <cuda_bf16.h>
#include <cstdint>

// Gridworld env step: warp-per-env union-window gather + smem-staged output
// shipped via ONE cp.async.bulk (TMA bulk store) per CTA.
// Output copy moves off the LSU/STG path onto the TMA engine (own
// outstanding-request machinery, full-line writes by construction).
//
// Inputs (metadata order):
//   0 grids (N,64,64) f32 | 1 energy (N,) f32 | 2 lut (5,) f32
//   3 agent_x (N,) i32 | 4 agent_y (N,) i32 | 5 agent_steps (unused)
//   6 actions (N,) i32 | 7 action_deltas (9,2) i32
// Output: obs (N, 6, 11, 11) f32

#define HW   64
#define VIEW 11
#define RAD  5
#define CELLS 121
#define OBS_PER_ENV 726
#define WPB 8               // warps (=envs) per block
#define BLOCK_OBS_BYTES (WPB * OBS_PER_ENV * 4)   // 23232, multiple of 16

__global__ __launch_bounds__(256)
void env_step_kernel(const float* __restrict__ grids,
                     const float* __restrict__ energy_in,
                     const float* __restrict__ lut,
                     const int*   __restrict__ agent_x,
                     const int*   __restrict__ agent_y,
                     const int*   __restrict__ actions,
                     const int*   __restrict__ deltas,
                     float*       __restrict__ out,
                     int n_envs)
{
    __shared__ float s_win[WPB][12][16];
    __shared__ __align__(16) float s_obs[WPB * OBS_PER_ENV];   // 23232 B

    const int wib   = threadIdx.x >> 5;
    const int lane  = threadIdx.x & 31;
    const int env0  = blockIdx.x * WPB;
    const int env   = env0 + wib;

    if (env < n_envs) {
        float (* __restrict__ win)[16] = s_win[wib];
        const float* __restrict__ g = grids + (size_t)env * (HW * HW);

        // ---- ROUND 1: independent scalar loads ----
        const int   a   = __ldg(actions   + env);
        const int   y0  = __ldg(agent_y   + env);
        const int   x0  = __ldg(agent_x   + env);
        const float en0 = __ldg(energy_in + env);
        const int   dval = (lane < 18) ? __ldg(deltas + lane) : 0;
        const float l0 = __ldg(lut + 0);
        const float l1 = __ldg(lut + 1);
        const float l2 = __ldg(lut + 2);
        const float l3 = __ldg(lut + 3);

        const int dy = __shfl_sync(0xffffffffu, dval, 2 * a);
        const int dx = __shfl_sync(0xffffffffu, dval, 2 * a + 1);

        const int nyc = min(max(y0 + dy, 0), HW - 1);
        const int nxc = min(max(x0 + dx, 0), HW - 1);

        // union-window origin (covers both 11x11 windows; extent <= 12x12)
        const int by = min(y0, nyc) - RAD;
        const int bx = min(x0, nxc) - RAD;
        const int cb = min(max(bx, 0) & ~3, HW - 16);     // 16B-aligned col base

        // ---- ROUND 2: single gather — 48 float4 tasks into smem ----
        #pragma unroll
        for (int it = 0; it < 2; it++) {
            const int task = lane + 32 * it;
            if (task < 48) {
                const int r  = task >> 2;
                const int s  = task & 3;
                const int gy = by + r;
                if ((unsigned)gy < (unsigned)HW) {
                    const float4 v = __ldg((const float4*)(g + gy * HW + cb + 4 * s));
                    *(float4*)&win[r][4 * s] = v;
                }
            }
        }
        __syncwarp();

        // ---- resolve move from smem ----
        const float tgt   = win[nyc - by][nxc - cb];
        const float stayc = win[y0  - by][x0  - cb];

        const bool  blocked  = (tgt == 1.0f);
        const int   ny = blocked ? y0 : nyc;
        const int   nx = blocked ? x0 : nxc;
        const float cell     = blocked ? stayc : tgt;
        const bool  food     = (cell == 2.0f);
        const bool  poison   = (cell == 3.0f);
        const bool  consumed = food | poison;
        const float reward   = (food ? 10.0f : 0.0f) - (poison ? 10.0f : 0.0f);
        const float energy   = en0 - 1.0f + reward;

        // ---- emit 6 channels into smem staging ----
        float* __restrict__ so = s_obs + wib * OBS_PER_ENV;
        #pragma unroll
        for (int j = 0; j < 4; j++) {
            const int c = lane + 32 * j;
            if (c < CELLS) {
                const int wy = c / VIEW - RAD;
                const int wx = c % VIEW - RAD;
                const int gy = ny + wy;
                const int gx = nx + wx;
                float v = 1.0f;                               // WALL padding
                if ((unsigned)gy < (unsigned)HW && (unsigned)gx < (unsigned)HW)
                    v = win[gy - by][gx - cb];
                if (consumed && c == 60) v = 0.0f;            // landed -> EMPTY
                const int   vi = (int)v;
                const float lv = (vi == 0) ? l0 : (vi == 1) ? l1 : (vi == 2) ? l2 : l3;
                so[0 * CELLS + c] = (v == 2.0f) ? 1.0f : 0.0f;
                so[1 * CELLS + c] = (v == 3.0f) ? 1.0f : 0.0f;
                so[2 * CELLS + c] = (v == 1.0f) ? 1.0f : 0.0f;
                so[3 * CELLS + c] = lv;
                so[4 * CELLS + c] = v;
                so[5 * CELLS + c] = energy;
            }
        }
    }

    __syncthreads();

    // ---- ship the whole block's output with ONE TMA bulk store ----
    const int nloc = min(WPB, n_envs - env0);
    if (nloc == WPB) {
        if (threadIdx.x == 0) {
            float* gdst = out + (size_t)env0 * OBS_PER_ENV;     // 16B-aligned
            unsigned int saddr;
            asm("{ .reg .u64 t; cvta.to.shared.u64 t, %1; cvt.u32.u64 %0, t; }"
                : "=r"(saddr) : "l"((const void*)s_obs));
            asm volatile("fence.proxy.async.shared::cta;" ::: "memory");
            asm volatile("cp.async.bulk.global.shared::cta.bulk_group [%0], [%1], %2;"
                         :: "l"(gdst), "r"(saddr), "r"((unsigned int)BLOCK_OBS_BYTES)
                         : "memory");
            asm volatile("cp.async.bulk.commit_group;" ::: "memory");
            asm volatile("cp.async.bulk.wait_group.read 0;" ::: "memory");
        }
    } else if (nloc > 0) {
        // tail block (unused for n_envs % 8 == 0): plain vector copy
        float2* __restrict__ dst = (float2*)(out + (size_t)env0 * OBS_PER_ENV);
        const float2* __restrict__ src = (const float2*)s_obs;
        const int n2 = nloc * (OBS_PER_ENV / 2);
        for (int i = threadIdx.x; i < n2; i += 256)
            dst[i] = src[i];
    }
}

extern "C" void kernel_launch(void* const* d_in, const int* in_sizes, int n_in,
                              void* d_out, int out_size)
{
    const float* grids   = (const float*)d_in[0];
    const float* energy  = (const float*)d_in[1];
    const float* lut     = (const float*)d_in[2];
    const int*   ax      = (const int*)  d_in[3];
    const int*   ay      = (const int*)  d_in[4];
    // d_in[5] agent_steps unused
    const int*   actions = (const int*)  d_in[6];
    const int*   deltas  = (const int*)  d_in[7];
    float*       out     = (float*)      d_out;

    const int n_envs = in_sizes[1];
    const int blocks = (n_envs + WPB - 1) / WPB;

    env_step_kernel<<<blocks, 256>>>(grids, energy, lut, ax, ay, actions, deltas, out, n_envs);
}

// round 14
// speedup vs baseline: 1.0182x; 1.0182x over previous
#include <cuda_runtime.h>
#include <cuda_bf16.h>
#include <cstdint>

// Gridworld env step: warp-per-env union-window gather, minimal-instruction
// emit via a per-warp 4-entry channel table (v in {0..3} -> float4
// {food,poison,wall,lut}), consumed-center baked into the smem window.
//
// Inputs (metadata order):
//   0 grids (N,64,64) f32 | 1 energy (N,) f32 | 2 lut (5,) f32
//   3 agent_x (N,) i32 | 4 agent_y (N,) i32 | 5 agent_steps (unused)
//   6 actions (N,) i32 | 7 action_deltas (9,2) i32
// Output: obs (N, 6, 11, 11) f32

#define HW   64
#define VIEW 11
#define RAD  5
#define CELLS 121
#define OBS_PER_ENV 726
#define WPB 8               // warps (=envs) per block

__global__ __launch_bounds__(256)
void env_step_kernel(const float* __restrict__ grids,
                     const float* __restrict__ energy_in,
                     const float* __restrict__ lut,
                     const int*   __restrict__ agent_x,
                     const int*   __restrict__ agent_y,
                     const int*   __restrict__ actions,
                     const int*   __restrict__ deltas,
                     float*       __restrict__ out,
                     int n_envs)
{
    __shared__ float  s_win[WPB][12][16];
    __shared__ float4 s_tab[WPB][4];       // per-warp channel table

    const int wib  = threadIdx.x >> 5;
    const int lane = threadIdx.x & 31;
    const int env  = blockIdx.x * WPB + wib;
    if (env >= n_envs) return;

    float (* __restrict__ win)[16] = s_win[wib];
    const float* __restrict__ g = grids + (size_t)env * (HW * HW);

    // ---- ROUND 1: independent scalar loads ----
    const int   a    = __ldg(actions   + env);
    const int   y0   = __ldg(agent_y   + env);
    const int   x0   = __ldg(agent_x   + env);
    const float en0  = __ldg(energy_in + env);
    const int   dval = (lane < 18) ? __ldg(deltas + lane) : 0;

    // build channel table: tab[v] = {v==2, v==3, v==1, lut[v]}
    if (lane < 4) {
        float4 t;
        t.x = (lane == 2) ? 1.0f : 0.0f;   // food
        t.y = (lane == 3) ? 1.0f : 0.0f;   // poison
        t.z = (lane == 1) ? 1.0f : 0.0f;   // wall
        t.w = __ldg(lut + lane);           // interestingness
        s_tab[wib][lane] = t;
    }

    const int dy = __shfl_sync(0xffffffffu, dval, 2 * a);
    const int dx = __shfl_sync(0xffffffffu, dval, 2 * a + 1);

    const int nyc = min(max(y0 + dy, 0), HW - 1);
    const int nxc = min(max(x0 + dx, 0), HW - 1);

    // union-window origin (covers both 11x11 windows; extent <= 12x12)
    const int by = min(y0, nyc) - RAD;
    const int bx = min(x0, nxc) - RAD;
    const int cb = min(max(bx, 0) & ~3, HW - 16);     // 16B-aligned col base

    // ---- ROUND 2: single gather — 48 float4 tasks into smem ----
    #pragma unroll
    for (int it = 0; it < 2; it++) {
        const int task = lane + 32 * it;
        if (task < 48) {
            const int r  = task >> 2;
            const int s  = task & 3;
            const int gy = by + r;
            if ((unsigned)gy < (unsigned)HW) {
                const float4 v = __ldg((const float4*)(g + gy * HW + cb + 4 * s));
                *(float4*)&win[r][4 * s] = v;
            }
        }
    }
    __syncwarp();

    // ---- resolve move (broadcast LDS) ----
    const float tgt   = win[nyc - by][nxc - cb];
    const float stayc = win[y0  - by][x0  - cb];

    const bool  blocked  = (tgt == 1.0f);
    const int   ny = blocked ? y0 : nyc;
    const int   nx = blocked ? x0 : nxc;
    const float cell     = blocked ? stayc : tgt;
    const bool  food     = (cell == 2.0f);
    const bool  poison   = (cell == 3.0f);
    const bool  consumed = food | poison;
    const float reward   = (food ? 10.0f : 0.0f) - (poison ? 10.0f : 0.0f);
    const float energy   = en0 - 1.0f + reward;

    // bake consumed landed-cell into window: becomes EMPTY
    if (lane == 0)
        win[ny - by][nx - cb] = consumed ? 0.0f : cell;
    __syncwarp();

    // ---- emit: per cell = 1 LDS + F2I + 1 LDS.128 + 6 STG ----
    const float4* __restrict__ tab = s_tab[wib];
    float* __restrict__ o = out + (size_t)env * OBS_PER_ENV;
    #pragma unroll
    for (int j = 0; j < 4; j++) {
        const int c = lane + 32 * j;
        if (c < CELLS) {
            const int wy = c / VIEW - RAD;
            const int wx = c % VIEW - RAD;
            const int gy = ny + wy;
            const int gx = nx + wx;
            float v = 1.0f;                               // WALL padding
            if ((unsigned)gy < (unsigned)HW && (unsigned)gx < (unsigned)HW)
                v = win[gy - by][gx - cb];
            const float4 t = tab[(int)v];
            float* oc = o + c;
            oc[0 * CELLS] = t.x;
            oc[1 * CELLS] = t.y;
            oc[2 * CELLS] = t.z;
            oc[3 * CELLS] = t.w;
            oc[4 * CELLS] = v;
            oc[5 * CELLS] = energy;
        }
    }
}

extern "C" void kernel_launch(void* const* d_in, const int* in_sizes, int n_in,
                              void* d_out, int out_size)
{
    const float* grids   = (const float*)d_in[0];
    const float* energy  = (const float*)d_in[1];
    const float* lut     = (const float*)d_in[2];
    const int*   ax      = (const int*)  d_in[3];
    const int*   ay      = (const int*)  d_in[4];
    // d_in[5] agent_steps unused
    const int*   actions = (const int*)  d_in[6];
    const int*   deltas  = (const int*)  d_in[7];
    float*       out     = (float*)      d_out;

    const int n_envs = in_sizes[1];
    const int blocks = (n_envs + WPB - 1) / WPB;

    env_step_kernel<<<blocks, 256>>>(grids, energy, lut, ax, ay, actions, deltas, out, n_envs);
}